// round 13
// baseline (speedup 1.0000x reference)
#include <cuda_runtime.h>
#include <cuda_fp16.h>
#include <math.h>
#include <stdint.h>

#define DIMV   100
#define TSTEPS 100
#define NT     256
#define MT     32          // rows per CTA -> 128 CTAs
#define AST2   116         // A row stride in u64 units (mod 16 == 4 -> conflict-free)
#define SST    102         // S row stride in floats

// weight pool: per layer, per k16-step: [npad][16] u32:
//   slot = n*16 + tq*4 + {0:hi(kp=tq),1:hi(kp=tq+4),2:lo(kp=tq),3:lo(kp=tq+4)}
#define OFF_L0 0
#define OFF_L1 22400
#define OFF_L2 64000
#define OFF_L3 105600
#define OFF_LO 147200
__device__ __align__(16) uint32_t g_Bpk[168832];

// ---------- helpers ----------
__device__ __forceinline__ void hsplit2(float f0, float f1, uint32_t& hi, uint32_t& lo) {
    __half h0 = __float2half_rn(f0), h1 = __float2half_rn(f1);
    __half l0 = __float2half_rn(f0 - __half2float(h0));
    __half l1 = __float2half_rn(f1 - __half2float(h1));
    hi = ((uint32_t)__half_as_ushort(h1) << 16) | __half_as_ushort(h0);
    lo = ((uint32_t)__half_as_ushort(l1) << 16) | __half_as_ushort(l0);
}
__device__ __forceinline__ void mma16816(float* c, const uint32_t* a, const uint32_t* b) {
    asm volatile("mma.sync.aligned.m16n8k16.row.col.f32.f16.f16.f32 "
        "{%0,%1,%2,%3}, {%4,%5,%6,%7}, {%8,%9}, {%0,%1,%2,%3};"
        : "+f"(c[0]), "+f"(c[1]), "+f"(c[2]), "+f"(c[3])
        : "r"(a[0]), "r"(a[1]), "r"(a[2]), "r"(a[3]), "r"(b[0]), "r"(b[1]));
}

// ---------- weight pack: fp16 split + transpose + fragment-quad interleave ----------
__global__ void pack_b(const float* __restrict__ W, int Kr, int Nr, int npad,
                       int ksteps, int off) {
    int idx = blockIdx.x * blockDim.x + threadIdx.x;
    if (idx >= ksteps * npad * 8) return;
    int ks = idx / (npad * 8), r = idx - ks * npad * 8, n = r >> 3, kp = r & 7;
    int k0 = ks * 16 + kp * 2, k1 = k0 + 1;
    float v0 = (k0 < Kr && n < Nr) ? W[(size_t)k0 * Nr + n] : 0.0f;
    float v1 = (k1 < Kr && n < Nr) ? W[(size_t)k1 * Nr + n] : 0.0f;
    uint32_t hi, lo; hsplit2(v0, v1, hi, lo);
    int tq = kp & 3, hs = kp >> 2;
    int b = off + ks * npad * 16 + n * 16 + tq * 4;
    g_Bpk[b + hs]     = hi;
    g_Bpk[b + 2 + hs] = lo;
}

// ---------- hidden-layer GEMM + epilogue (1m x 8n grid, mf=2, 32 rows/warp) ----------
// Reads Ain, writes Aout (ping-pong). ONE sync at the end.
template<int KS>
__device__ __forceinline__ void gemm_hidden(
    const uint2* __restrict__ Ain, uint2* __restrict__ Aout,
    const uint32_t* pool, const float* bias, int wn, int g, int tq)
{
    float acc[2][4][4];
    #pragma unroll
    for (int m = 0; m < 2; ++m)
        #pragma unroll
        for (int b = 0; b < 4; ++b)
            #pragma unroll
            for (int c = 0; c < 4; ++c) acc[m][b][c] = 0.0f;

    const uint32_t* pb = pool + (size_t)g * 16 + tq * 4;
    uint4 B[2][4];
    #pragma unroll
    for (int j = 0; j < 4; ++j) {
        int nt = wn + 8 * j;
        if (nt < 25) B[0][j] = *(const uint4*)(pb + nt * 128);
    }

    #pragma unroll
    for (int ks = 0; ks < KS; ++ks) {
        const int cb = ks & 1;
        if (ks + 1 < KS) {
            const uint32_t* p2 = pb + (size_t)(ks + 1) * 3200;
            #pragma unroll
            for (int j = 0; j < 4; ++j) {
                int nt = wn + 8 * j;
                if (nt < 25) B[cb ^ 1][j] = *(const uint4*)(p2 + nt * 128);
            }
        }
        uint32_t Ah[2][4], Al[2][4];
        #pragma unroll
        for (int mf = 0; mf < 2; ++mf)
            #pragma unroll
            for (int r = 0; r < 4; ++r) {
                int row = mf * 16 + g + (r & 1) * 8;
                int kp  = ks * 8 + tq + (r >> 1) * 4;
                uint2 v = Ain[row * AST2 + kp];
                Ah[mf][r] = v.x; Al[mf][r] = v.y;
            }
        #pragma unroll
        for (int j = 0; j < 4; ++j) {
            int nt = wn + 8 * j;
            if (nt < 25) {
                uint32_t Bh[2] = { B[cb][j].x, B[cb][j].y };
                uint32_t Bl[2] = { B[cb][j].z, B[cb][j].w };
                #pragma unroll
                for (int mf = 0; mf < 2; ++mf) {
                    mma16816(acc[mf][j], Ah[mf], Bh);
                    mma16816(acc[mf][j], Ah[mf], Bl);
                    mma16816(acc[mf][j], Al[mf], Bh);
                }
            }
        }
    }

    #pragma unroll
    for (int j = 0; j < 4; ++j) {
        int nt = wn + 8 * j;
        if (nt < 25) {
            int n0 = nt * 8 + tq * 2;
            float bv0 = bias[n0], bv1 = bias[n0 + 1];
            int kp = nt * 4 + tq;
            #pragma unroll
            for (int mf = 0; mf < 2; ++mf) {
                int row = mf * 16 + g;
                uint2 v;
                hsplit2(fmaxf(acc[mf][j][0] + bv0, 0.0f),
                        fmaxf(acc[mf][j][1] + bv1, 0.0f), v.x, v.y);
                Aout[row * AST2 + kp] = v;
                hsplit2(fmaxf(acc[mf][j][2] + bv0, 0.0f),
                        fmaxf(acc[mf][j][3] + bv1, 0.0f), v.x, v.y);
                Aout[(row + 8) * AST2 + kp] = v;
            }
        }
    }
    __syncthreads();   // Aout visible; everyone past Ain reads
}

// ---------- main persistent kernel ----------
// smem: A[2][32][116] uint2 = 59392 | S 13056 | sbv 3600 | tgs 404  -> ~76.5 KB
#define SMEM_BYTES 76800

__global__ void __launch_bounds__(NT, 1)
control_solver_hmma(
    const float* __restrict__ S0, const float* __restrict__ tg,
    const float* __restrict__ dW,
    const float* __restrict__ b0, const float* __restrict__ b1,
    const float* __restrict__ b2, const float* __restrict__ b3,
    const float* __restrict__ bout, float* __restrict__ out)
{
    extern __shared__ __align__(16) char smc[];
    uint2* A0b = (uint2*)smc;                        // buffer 0
    uint2* A1b = A0b + MT * AST2;                    // buffer 1
    float* S   = (float*)(A1b + MT * AST2);
    float* sbv = S + MT * SST;                       // biases 0..899
    float* tgs = sbv + 900;                          // timegrid

    const int tid = threadIdx.x, warp = tid >> 5, lane = tid & 31;
    const int g = lane >> 2, tq = lane & 3;
    const int wn = warp;
    const int gm0 = blockIdx.x * MT;

    for (int i = tid; i < 200; i += NT) {
        sbv[i] = b0[i]; sbv[200 + i] = b1[i]; sbv[400 + i] = b2[i]; sbv[600 + i] = b3[i];
        if (i < 100) sbv[800 + i] = bout[i];
    }
    for (int i = tid; i <= TSTEPS; i += NT) tgs[i] = tg[i];
    for (int i = tid; i < MT * DIMV; i += NT) {
        int m = i / DIMV, c = i - m * DIMV;
        S[m * SST + c] = S0[(size_t)(gm0 + m) * DIMV + c];
    }
    for (int i = tid; i < MT * 4; i += NT) {         // zero pad kp 100..103, both buffers
        int row = i >> 2, kp = 100 + (i & 3);
        A0b[row * AST2 + kp] = make_uint2(0, 0);
        A1b[row * AST2 + kp] = make_uint2(0, 0);
    }
    __syncthreads();
    const float h = tgs[1] - tgs[0];
    const float sqh = sqrtf(h);

    for (int t = 0; t < TSTEPS; ++t) {
        // build A0 = [t | S | 0pad] into buffer 0, kpairs 0..55
        {
            int row = tid >> 3, q = tid & 7;
            float tval = tgs[t];
            #pragma unroll
            for (int jj = 0; jj < 7; ++jj) {
                int j = q * 7 + jj, k0 = 2 * j;
                float f0 = (k0 == 0) ? tval : ((k0 <= 100) ? S[row * SST + k0 - 1] : 0.0f);
                float f1 = (k0 + 1 <= 100) ? S[row * SST + k0] : 0.0f;
                uint2 v; hsplit2(f0, f1, v.x, v.y);
                A0b[row * AST2 + j] = v;
            }
        }
        __syncthreads();

        gemm_hidden<7> (A0b, A1b, g_Bpk + OFF_L0, sbv,       wn, g, tq);
        gemm_hidden<13>(A1b, A0b, g_Bpk + OFF_L1, sbv + 200, wn, g, tq);
        gemm_hidden<13>(A0b, A1b, g_Bpk + OFF_L2, sbv + 400, wn, g, tq);
        gemm_hidden<13>(A1b, A0b, g_Bpk + OFF_L3, sbv + 600, wn, g, tq);

        // ---- output layer (reads buffer 0; 13 ksteps, npad 104) ----
        float acc[2][2][4];
        #pragma unroll
        for (int m = 0; m < 2; ++m)
            #pragma unroll
            for (int b = 0; b < 2; ++b)
                #pragma unroll
                for (int c = 0; c < 4; ++c) acc[m][b][c] = 0.0f;

        {
            const uint32_t* pb = g_Bpk + OFF_LO + (size_t)g * 16 + tq * 4;
            uint4 B[2][2];
            #pragma unroll
            for (int j = 0; j < 2; ++j) {
                int nt = wn + 8 * j;
                if (nt < 13) B[0][j] = *(const uint4*)(pb + nt * 128);
            }
            #pragma unroll
            for (int ks = 0; ks < 13; ++ks) {
                const int cb = ks & 1;
                if (ks + 1 < 13) {
                    const uint32_t* p2 = pb + (size_t)(ks + 1) * 1664;
                    #pragma unroll
                    for (int j = 0; j < 2; ++j) {
                        int nt = wn + 8 * j;
                        if (nt < 13) B[cb ^ 1][j] = *(const uint4*)(p2 + nt * 128);
                    }
                }
                uint32_t Ah[2][4], Al[2][4];
                #pragma unroll
                for (int mf = 0; mf < 2; ++mf)
                    #pragma unroll
                    for (int r = 0; r < 4; ++r) {
                        int row = mf * 16 + g + (r & 1) * 8;
                        int kp  = ks * 8 + tq + (r >> 1) * 4;
                        uint2 v = A0b[row * AST2 + kp];
                        Ah[mf][r] = v.x; Al[mf][r] = v.y;
                    }
                #pragma unroll
                for (int j = 0; j < 2; ++j) {
                    int nt = wn + 8 * j;
                    if (nt < 13) {
                        uint32_t Bh[2] = { B[cb][j].x, B[cb][j].y };
                        uint32_t Bl[2] = { B[cb][j].z, B[cb][j].w };
                        #pragma unroll
                        for (int mf = 0; mf < 2; ++mf) {
                            mma16816(acc[mf][j], Ah[mf], Bh);
                            mma16816(acc[mf][j], Ah[mf], Bl);
                            mma16816(acc[mf][j], Al[mf], Bh);
                        }
                    }
                }
            }
        }

        // ---- SDE epilogue: u = D + bout; err->out (rmw); S update ----
        #pragma unroll
        for (int j = 0; j < 2; ++j) {
            int nt = wn + 8 * j;
            if (nt < 13) {
                int n0 = nt * 8 + tq * 2;
                if (n0 < 100) {
                    float bv0 = sbv[800 + n0], bv1 = sbv[800 + n0 + 1];
                    #pragma unroll
                    for (int mf = 0; mf < 2; ++mf)
                        #pragma unroll
                        for (int hf = 0; hf < 2; ++hf) {
                            int m = mf * 16 + g + 8 * hf;
                            float u0 = acc[mf][j][2 * hf]     + bv0;
                            float u1 = acc[mf][j][2 * hf + 1] + bv1;
                            float2 dw = *(const float2*)(dW + (size_t)(gm0 + m) * 10100
                                                            + (size_t)t * DIMV + n0);
                            float s0 = S[m * SST + n0]     + u0 * (h + sqh * dw.x);
                            float s1 = S[m * SST + n0 + 1] + u1 * (h + sqh * dw.y);
                            float2* op = (float2*)(out + (size_t)(gm0 + m) * DIMV + n0);
                            float2 prev = (t == 0) ? make_float2(0.0f, 0.0f) : *op;
                            float o0 = prev.x + u0 * u0 * h;
                            float o1 = prev.y + u1 * u1 * h;
                            if (t == TSTEPS - 1) { o0 += s0 * s0; o1 += s1 * s1; }
                            else { S[m * SST + n0] = s0; S[m * SST + n0 + 1] = s1; }
                            *op = make_float2(o0, o1);
                        }
                }
            }
        }
        __syncthreads();   // S stable before next build_A0 (which also rewrites A0b)
    }
}

extern "C" void kernel_launch(void* const* d_in, const int* in_sizes, int n_in,
                              void* d_out, int out_size) {
    const float* S0   = (const float*)d_in[0];
    const float* tg   = (const float*)d_in[1];
    const float* dW   = (const float*)d_in[2];
    const float* W0   = (const float*)d_in[3];
    const float* b0   = (const float*)d_in[4];
    const float* W1   = (const float*)d_in[5];
    const float* b1   = (const float*)d_in[6];
    const float* W2   = (const float*)d_in[7];
    const float* b2   = (const float*)d_in[8];
    const float* W3   = (const float*)d_in[9];
    const float* b3   = (const float*)d_in[10];
    const float* Wout = (const float*)d_in[11];
    const float* bout = (const float*)d_in[12];
    float* out = (float*)d_out;

    pack_b<<<(7  * 200 * 8 + 255) / 256, 256>>>(W0,   101, 200, 200, 7,  OFF_L0);
    pack_b<<<(13 * 200 * 8 + 255) / 256, 256>>>(W1,   200, 200, 200, 13, OFF_L1);
    pack_b<<<(13 * 200 * 8 + 255) / 256, 256>>>(W2,   200, 200, 200, 13, OFF_L2);
    pack_b<<<(13 * 200 * 8 + 255) / 256, 256>>>(W3,   200, 200, 200, 13, OFF_L3);
    pack_b<<<(13 * 104 * 8 + 255) / 256, 256>>>(Wout, 200, 100, 104, 13, OFF_LO);

    cudaFuncSetAttribute(control_solver_hmma,
                         cudaFuncAttributeMaxDynamicSharedMemorySize, SMEM_BYTES);
    control_solver_hmma<<<4096 / MT, NT, SMEM_BYTES>>>(
        S0, tg, dW, b0, b1, b2, b3, bout, out);
}

// round 14
// speedup vs baseline: 1.3832x; 1.3832x over previous
#include <cuda_runtime.h>
#include <cuda_fp16.h>
#include <math.h>
#include <stdint.h>

#define DIMV   100
#define TSTEPS 100
#define NT     256
#define MT     32          // rows per CTA -> 128 CTAs
#define AST    108         // A row stride in u32 (conflict-free)
#define SST    102         // S row stride in floats
#define EST    100         // err row stride in floats

// weight pool: per layer, per k16-step: [npad][16] u32:
//   slot = n*16 + tq*4 + {0:hi(kp=tq),1:hi(kp=tq+4),2:lo(kp=tq),3:lo(kp=tq+4)}
#define OFF_L0 0           // 7  ksteps * 200*16 = 22400
#define OFF_L1 22400       // 13 * 3200 = 41600
#define OFF_L2 64000
#define OFF_L3 105600
#define OFF_LO 147200      // 13 * 104*16 = 21632
__device__ __align__(16) uint32_t g_Bpk[168832];

// ---------- helpers ----------
__device__ __forceinline__ void hsplit2(float f0, float f1, uint32_t& hi, uint32_t& lo) {
    __half h0 = __float2half_rn(f0), h1 = __float2half_rn(f1);
    __half l0 = __float2half_rn(f0 - __half2float(h0));
    __half l1 = __float2half_rn(f1 - __half2float(h1));
    hi = ((uint32_t)__half_as_ushort(h1) << 16) | __half_as_ushort(h0);
    lo = ((uint32_t)__half_as_ushort(l1) << 16) | __half_as_ushort(l0);
}
__device__ __forceinline__ void mma16816(float* c, const uint32_t* a, const uint32_t* b) {
    asm volatile("mma.sync.aligned.m16n8k16.row.col.f32.f16.f16.f32 "
        "{%0,%1,%2,%3}, {%4,%5,%6,%7}, {%8,%9}, {%0,%1,%2,%3};"
        : "+f"(c[0]), "+f"(c[1]), "+f"(c[2]), "+f"(c[3])
        : "r"(a[0]), "r"(a[1]), "r"(a[2]), "r"(a[3]), "r"(b[0]), "r"(b[1]));
}

// ---------- weight pack: fp16 split + transpose + fragment-quad interleave ----------
__global__ void pack_b(const float* __restrict__ W, int Kr, int Nr, int npad,
                       int ksteps, int off) {
    int idx = blockIdx.x * blockDim.x + threadIdx.x;
    if (idx >= ksteps * npad * 8) return;
    int ks = idx / (npad * 8), r = idx - ks * npad * 8, n = r >> 3, kp = r & 7;
    int k0 = ks * 16 + kp * 2, k1 = k0 + 1;
    float v0 = (k0 < Kr && n < Nr) ? W[(size_t)k0 * Nr + n] : 0.0f;
    float v1 = (k1 < Kr && n < Nr) ? W[(size_t)k1 * Nr + n] : 0.0f;
    uint32_t hi, lo; hsplit2(v0, v1, hi, lo);
    int tq = kp & 3, hs = kp >> 2;
    int b = off + ks * npad * 16 + n * 16 + tq * 4;
    g_Bpk[b + hs]     = hi;
    g_Bpk[b + 2 + hs] = lo;
}

// ---------- hidden-layer GEMM + epilogue (1m x 8n grid, mf=2, 32 rows/warp) ----------
template<int KS>
__device__ __forceinline__ void gemm_hidden(
    uint32_t* Ahi, uint32_t* Alo, const uint32_t* pool, const float* bias,
    int wn, int g, int tq)
{
    float acc[2][4][4];
    #pragma unroll
    for (int m = 0; m < 2; ++m)
        #pragma unroll
        for (int b = 0; b < 4; ++b)
            #pragma unroll
            for (int c = 0; c < 4; ++c) acc[m][b][c] = 0.0f;

    const uint32_t* pb = pool + (size_t)g * 16 + tq * 4;
    uint4 B[2][4];
    #pragma unroll
    for (int j = 0; j < 4; ++j) {
        int nt = wn + 8 * j;
        if (nt < 25) B[0][j] = *(const uint4*)(pb + nt * 128);
    }

    #pragma unroll
    for (int ks = 0; ks < KS; ++ks) {
        const int cb = ks & 1;
        if (ks + 1 < KS) {
            const uint32_t* p2 = pb + (size_t)(ks + 1) * 3200;
            #pragma unroll
            for (int j = 0; j < 4; ++j) {
                int nt = wn + 8 * j;
                if (nt < 25) B[cb ^ 1][j] = *(const uint4*)(p2 + nt * 128);
            }
        }
        uint32_t Ah[2][4], Al[2][4];
        #pragma unroll
        for (int mf = 0; mf < 2; ++mf)
            #pragma unroll
            for (int r = 0; r < 4; ++r) {
                int row = mf * 16 + g + (r & 1) * 8;
                int kp  = ks * 8 + tq + (r >> 1) * 4;
                Ah[mf][r] = Ahi[row * AST + kp];
                Al[mf][r] = Alo[row * AST + kp];
            }
        #pragma unroll
        for (int j = 0; j < 4; ++j) {
            int nt = wn + 8 * j;
            if (nt < 25) {
                uint32_t Bh[2] = { B[cb][j].x, B[cb][j].y };
                uint32_t Bl[2] = { B[cb][j].z, B[cb][j].w };
                #pragma unroll
                for (int mf = 0; mf < 2; ++mf) {
                    mma16816(acc[mf][j], Ah[mf], Bh);
                    mma16816(acc[mf][j], Ah[mf], Bl);
                    mma16816(acc[mf][j], Al[mf], Bh);
                }
            }
        }
    }
    __syncthreads();   // all reads of A done before overwriting

    #pragma unroll
    for (int j = 0; j < 4; ++j) {
        int nt = wn + 8 * j;
        if (nt < 25) {
            int n0 = nt * 8 + tq * 2;
            float bv0 = bias[n0], bv1 = bias[n0 + 1];
            int kp = nt * 4 + tq;
            #pragma unroll
            for (int mf = 0; mf < 2; ++mf) {
                int row = mf * 16 + g;
                uint32_t hi, lo;
                hsplit2(fmaxf(acc[mf][j][0] + bv0, 0.0f),
                        fmaxf(acc[mf][j][1] + bv1, 0.0f), hi, lo);
                Ahi[row * AST + kp] = hi; Alo[row * AST + kp] = lo;
                hsplit2(fmaxf(acc[mf][j][2] + bv0, 0.0f),
                        fmaxf(acc[mf][j][3] + bv1, 0.0f), hi, lo);
                Ahi[(row + 8) * AST + kp] = hi; Alo[(row + 8) * AST + kp] = lo;
            }
        }
    }
    __syncthreads();   // new A visible before next layer reads
}

// ---------- main persistent kernel ----------
// smem: Ahi 13824 | Alo 13824 | S 13056 | errs 12800 | sbv 3600 | tgs 404 -> ~57.5 KB
#define SMEM_BYTES 58000

__global__ void __launch_bounds__(NT, 1)
control_solver_hmma(
    const float* __restrict__ S0, const float* __restrict__ tg,
    const float* __restrict__ dW,
    const float* __restrict__ b0, const float* __restrict__ b1,
    const float* __restrict__ b2, const float* __restrict__ b3,
    const float* __restrict__ bout, float* __restrict__ out)
{
    extern __shared__ __align__(16) char smc[];
    uint32_t* Ahi = (uint32_t*)smc;                  // 32*108*4
    uint32_t* Alo = Ahi + MT * AST;
    float* S      = (float*)(Alo + MT * AST);        // 32*102*4
    float* errs   = S + MT * SST;                    // 32*100*4
    float* sbv    = errs + MT * EST;                 // 900 biases
    float* tgs    = sbv + 900;                       // 101 timegrid

    const int tid = threadIdx.x, warp = tid >> 5, lane = tid & 31;
    const int g = lane >> 2, tq = lane & 3;
    const int wn = warp;                              // 1m x 8n
    const int gm0 = blockIdx.x * MT;

    for (int i = tid; i < 200; i += NT) {
        sbv[i] = b0[i]; sbv[200 + i] = b1[i]; sbv[400 + i] = b2[i]; sbv[600 + i] = b3[i];
        if (i < 100) sbv[800 + i] = bout[i];
    }
    for (int i = tid; i <= TSTEPS; i += NT) tgs[i] = tg[i];
    for (int i = tid; i < MT * DIMV; i += NT) {
        int m = i / DIMV, c = i - m * DIMV;
        S[m * SST + c] = S0[(size_t)(gm0 + m) * DIMV + c];
        errs[m * EST + c] = 0.0f;
    }
    for (int i = tid; i < MT * 8; i += NT) {         // zero A kpairs 100..107
        int row = i >> 3, kp = 100 + (i & 7);
        Ahi[row * AST + kp] = 0; Alo[row * AST + kp] = 0;
    }
    __syncthreads();
    const float h = tgs[1] - tgs[0];
    const float sqh = sqrtf(h);

    for (int t = 0; t < TSTEPS; ++t) {
        // build A0 = [t | S | 0pad] as fp16 hi/lo, kpairs 0..55
        {
            int row = tid >> 3, q = tid & 7;
            float tval = tgs[t];
            #pragma unroll
            for (int jj = 0; jj < 7; ++jj) {
                int j = q * 7 + jj, k0 = 2 * j;
                float f0 = (k0 == 0) ? tval : ((k0 <= 100) ? S[row * SST + k0 - 1] : 0.0f);
                float f1 = (k0 + 1 <= 100) ? S[row * SST + k0] : 0.0f;
                uint32_t hi, lo; hsplit2(f0, f1, hi, lo);
                Ahi[row * AST + j] = hi; Alo[row * AST + j] = lo;
            }
        }
        __syncthreads();   // A0 visible to all warps

        // ---- prefetch dW for this step (used ~40k cycles later in epilogue) ----
        float2 dwreg[2][2][2];
        #pragma unroll
        for (int j = 0; j < 2; ++j) {
            int nt = wn + 8 * j;
            if (nt < 13) {
                int n0 = nt * 8 + tq * 2;
                if (n0 < 100) {
                    #pragma unroll
                    for (int mf = 0; mf < 2; ++mf)
                        #pragma unroll
                        for (int hf = 0; hf < 2; ++hf) {
                            int m = mf * 16 + g + 8 * hf;
                            dwreg[j][mf][hf] = *(const float2*)(
                                dW + (size_t)(gm0 + m) * 10100 + (size_t)t * DIMV + n0);
                        }
                }
            }
        }

        gemm_hidden<7> (Ahi, Alo, g_Bpk + OFF_L0, sbv,       wn, g, tq);
        gemm_hidden<13>(Ahi, Alo, g_Bpk + OFF_L1, sbv + 200, wn, g, tq);
        gemm_hidden<13>(Ahi, Alo, g_Bpk + OFF_L2, sbv + 400, wn, g, tq);
        gemm_hidden<13>(Ahi, Alo, g_Bpk + OFF_L3, sbv + 600, wn, g, tq);

        // ---- output layer (13 ksteps, npad 104, n-tiles wn + 8j, j<2) ----
        float acc[2][2][4];
        #pragma unroll
        for (int m = 0; m < 2; ++m)
            #pragma unroll
            for (int b = 0; b < 2; ++b)
                #pragma unroll
                for (int c = 0; c < 4; ++c) acc[m][b][c] = 0.0f;

        {
            const uint32_t* pb = g_Bpk + OFF_LO + (size_t)g * 16 + tq * 4;
            uint4 B[2][2];
            #pragma unroll
            for (int j = 0; j < 2; ++j) {
                int nt = wn + 8 * j;
                if (nt < 13) B[0][j] = *(const uint4*)(pb + nt * 128);
            }
            #pragma unroll
            for (int ks = 0; ks < 13; ++ks) {
                const int cb = ks & 1;
                if (ks + 1 < 13) {
                    const uint32_t* p2 = pb + (size_t)(ks + 1) * 1664;
                    #pragma unroll
                    for (int j = 0; j < 2; ++j) {
                        int nt = wn + 8 * j;
                        if (nt < 13) B[cb ^ 1][j] = *(const uint4*)(p2 + nt * 128);
                    }
                }
                uint32_t Ah[2][4], Al[2][4];
                #pragma unroll
                for (int mf = 0; mf < 2; ++mf)
                    #pragma unroll
                    for (int r = 0; r < 4; ++r) {
                        int row = mf * 16 + g + (r & 1) * 8;
                        int kp  = ks * 8 + tq + (r >> 1) * 4;
                        Ah[mf][r] = Ahi[row * AST + kp];
                        Al[mf][r] = Alo[row * AST + kp];
                    }
                #pragma unroll
                for (int j = 0; j < 2; ++j) {
                    int nt = wn + 8 * j;
                    if (nt < 13) {
                        uint32_t Bh[2] = { B[cb][j].x, B[cb][j].y };
                        uint32_t Bl[2] = { B[cb][j].z, B[cb][j].w };
                        #pragma unroll
                        for (int mf = 0; mf < 2; ++mf) {
                            mma16816(acc[mf][j], Ah[mf], Bh);
                            mma16816(acc[mf][j], Ah[mf], Bl);
                            mma16816(acc[mf][j], Al[mf], Bh);
                        }
                    }
                }
            }
        }
        __syncthreads();

        // ---- SDE epilogue: u = D + bout; err in smem; S update; out only at end ----
        #pragma unroll
        for (int j = 0; j < 2; ++j) {
            int nt = wn + 8 * j;
            if (nt < 13) {
                int n0 = nt * 8 + tq * 2;
                if (n0 < 100) {
                    float bv0 = sbv[800 + n0], bv1 = sbv[800 + n0 + 1];
                    #pragma unroll
                    for (int mf = 0; mf < 2; ++mf)
                        #pragma unroll
                        for (int hf = 0; hf < 2; ++hf) {
                            int m = mf * 16 + g + 8 * hf;
                            float u0 = acc[mf][j][2 * hf]     + bv0;
                            float u1 = acc[mf][j][2 * hf + 1] + bv1;
                            float2 dw = dwreg[j][mf][hf];
                            float s0 = S[m * SST + n0]     + u0 * (h + sqh * dw.x);
                            float s1 = S[m * SST + n0 + 1] + u1 * (h + sqh * dw.y);
                            float e0 = errs[m * EST + n0]     + u0 * u0 * h;
                            float e1 = errs[m * EST + n0 + 1] + u1 * u1 * h;
                            if (t == TSTEPS - 1) {
                                float2* op = (float2*)(out + (size_t)(gm0 + m) * DIMV + n0);
                                *op = make_float2(e0 + s0 * s0, e1 + s1 * s1);
                            } else {
                                S[m * SST + n0] = s0; S[m * SST + n0 + 1] = s1;
                                errs[m * EST + n0] = e0; errs[m * EST + n0 + 1] = e1;
                            }
                        }
                }
            }
        }
        __syncthreads();   // S stable before next build_A0
    }
}

extern "C" void kernel_launch(void* const* d_in, const int* in_sizes, int n_in,
                              void* d_out, int out_size) {
    const float* S0   = (const float*)d_in[0];
    const float* tg   = (const float*)d_in[1];
    const float* dW   = (const float*)d_in[2];
    const float* W0   = (const float*)d_in[3];
    const float* b0   = (const float*)d_in[4];
    const float* W1   = (const float*)d_in[5];
    const float* b1   = (const float*)d_in[6];
    const float* W2   = (const float*)d_in[7];
    const float* b2   = (const float*)d_in[8];
    const float* W3   = (const float*)d_in[9];
    const float* b3   = (const float*)d_in[10];
    const float* Wout = (const float*)d_in[11];
    const float* bout = (const float*)d_in[12];
    float* out = (float*)d_out;

    pack_b<<<(7  * 200 * 8 + 255) / 256, 256>>>(W0,   101, 200, 200, 7,  OFF_L0);
    pack_b<<<(13 * 200 * 8 + 255) / 256, 256>>>(W1,   200, 200, 200, 13, OFF_L1);
    pack_b<<<(13 * 200 * 8 + 255) / 256, 256>>>(W2,   200, 200, 200, 13, OFF_L2);
    pack_b<<<(13 * 200 * 8 + 255) / 256, 256>>>(W3,   200, 200, 200, 13, OFF_L3);
    pack_b<<<(13 * 104 * 8 + 255) / 256, 256>>>(Wout, 200, 100, 104, 13, OFF_LO);

    cudaFuncSetAttribute(control_solver_hmma,
                         cudaFuncAttributeMaxDynamicSharedMemorySize, SMEM_BYTES);
    control_solver_hmma<<<4096 / MT, NT, SMEM_BYTES>>>(
        S0, tg, dW, b0, b1, b2, b3, bout, out);
}

// round 15
// speedup vs baseline: 1.4446x; 1.0444x over previous
#include <cuda_runtime.h>
#include <cuda_fp16.h>
#include <math.h>
#include <stdint.h>

#define DIMV   100
#define TSTEPS 100
#define NT     256
#define MT     32          // rows per CTA -> 128 CTAs
#define AST    108         // A row stride in u32 (conflict-free for LDSM phases)
#define SST    102         // S row stride in floats
#define EST    100         // err row stride in floats
#define MFOFF  (16*AST*4)  // byte offset of mf=1 tile (6912)

// weight pool: per layer, per k16-step: [npad][16] u32:
//   slot = n*16 + tq*4 + {0:hi(kp=tq),1:hi(kp=tq+4),2:lo(kp=tq),3:lo(kp=tq+4)}
#define OFF_L0 0
#define OFF_L1 22400
#define OFF_L2 64000
#define OFF_L3 105600
#define OFF_LO 147200
__device__ __align__(16) uint32_t g_Bpk[168832];

// ---------- helpers ----------
__device__ __forceinline__ uint32_t smem_u32(const void* p) {
    uint32_t a;
    asm("{ .reg .u64 t; cvta.to.shared.u64 t, %1; cvt.u32.u64 %0, t; }" : "=r"(a) : "l"(p));
    return a;
}
__device__ __forceinline__ void hsplit2(float f0, float f1, uint32_t& hi, uint32_t& lo) {
    __half h0 = __float2half_rn(f0), h1 = __float2half_rn(f1);
    __half l0 = __float2half_rn(f0 - __half2float(h0));
    __half l1 = __float2half_rn(f1 - __half2float(h1));
    hi = ((uint32_t)__half_as_ushort(h1) << 16) | __half_as_ushort(h0);
    lo = ((uint32_t)__half_as_ushort(l1) << 16) | __half_as_ushort(l0);
}
__device__ __forceinline__ void mma16816(float* c, const uint32_t* a, const uint32_t* b) {
    asm volatile("mma.sync.aligned.m16n8k16.row.col.f32.f16.f16.f32 "
        "{%0,%1,%2,%3}, {%4,%5,%6,%7}, {%8,%9}, {%0,%1,%2,%3};"
        : "+f"(c[0]), "+f"(c[1]), "+f"(c[2]), "+f"(c[3])
        : "r"(a[0]), "r"(a[1]), "r"(a[2]), "r"(a[3]), "r"(b[0]), "r"(b[1]));
}
__device__ __forceinline__ void ldsm4(uint32_t* r, uint32_t addr) {
    asm volatile("ldmatrix.sync.aligned.m8n8.x4.shared.b16 {%0,%1,%2,%3}, [%4];"
        : "=r"(r[0]), "=r"(r[1]), "=r"(r[2]), "=r"(r[3]) : "r"(addr));
}

// ---------- weight pack: fp16 split + transpose + fragment-quad interleave ----------
__global__ void pack_b(const float* __restrict__ W, int Kr, int Nr, int npad,
                       int ksteps, int off) {
    int idx = blockIdx.x * blockDim.x + threadIdx.x;
    if (idx >= ksteps * npad * 8) return;
    int ks = idx / (npad * 8), r = idx - ks * npad * 8, n = r >> 3, kp = r & 7;
    int k0 = ks * 16 + kp * 2, k1 = k0 + 1;
    float v0 = (k0 < Kr && n < Nr) ? W[(size_t)k0 * Nr + n] : 0.0f;
    float v1 = (k1 < Kr && n < Nr) ? W[(size_t)k1 * Nr + n] : 0.0f;
    uint32_t hi, lo; hsplit2(v0, v1, hi, lo);
    int tq = kp & 3, hs = kp >> 2;
    int b = off + ks * npad * 16 + n * 16 + tq * 4;
    g_Bpk[b + hs]     = hi;
    g_Bpk[b + 2 + hs] = lo;
}

// ---------- hidden-layer GEMM + epilogue (1m x 8n grid, mf=2, 32 rows/warp) ----------
// Reads A via ldmatrix from (inhi, inlo); writes (outhi, outlo). ONE sync at the end.
template<int KS>
__device__ __forceinline__ void gemm_hidden(
    uint32_t inhi, uint32_t inlo, uint32_t* outhi, uint32_t* outlo,
    const uint32_t* pool, const float* bias, int wn, int g, int tq)
{
    float acc[2][4][4];
    #pragma unroll
    for (int m = 0; m < 2; ++m)
        #pragma unroll
        for (int b = 0; b < 4; ++b)
            #pragma unroll
            for (int c = 0; c < 4; ++c) acc[m][b][c] = 0.0f;

    const uint32_t* pb = pool + (size_t)g * 16 + tq * 4;
    uint4 B[2][4];
    #pragma unroll
    for (int j = 0; j < 4; ++j) {
        int nt = wn + 8 * j;
        if (nt < 25) B[0][j] = *(const uint4*)(pb + nt * 128);
    }

    #pragma unroll
    for (int ks = 0; ks < KS; ++ks) {
        const int cb = ks & 1;
        if (ks + 1 < KS) {
            const uint32_t* p2 = pb + (size_t)(ks + 1) * 3200;
            #pragma unroll
            for (int j = 0; j < 4; ++j) {
                int nt = wn + 8 * j;
                if (nt < 25) B[cb ^ 1][j] = *(const uint4*)(p2 + nt * 128);
            }
        }
        uint32_t Ah[2][4], Al[2][4];
        ldsm4(Ah[0], inhi + ks * 32);
        ldsm4(Ah[1], inhi + MFOFF + ks * 32);
        ldsm4(Al[0], inlo + ks * 32);
        ldsm4(Al[1], inlo + MFOFF + ks * 32);
        #pragma unroll
        for (int j = 0; j < 4; ++j) {
            int nt = wn + 8 * j;
            if (nt < 25) {
                uint32_t Bh[2] = { B[cb][j].x, B[cb][j].y };
                uint32_t Bl[2] = { B[cb][j].z, B[cb][j].w };
                #pragma unroll
                for (int mf = 0; mf < 2; ++mf) {
                    mma16816(acc[mf][j], Ah[mf], Bh);
                    mma16816(acc[mf][j], Ah[mf], Bl);
                    mma16816(acc[mf][j], Al[mf], Bh);
                }
            }
        }
    }

    #pragma unroll
    for (int j = 0; j < 4; ++j) {
        int nt = wn + 8 * j;
        if (nt < 25) {
            int n0 = nt * 8 + tq * 2;
            float bv0 = bias[n0], bv1 = bias[n0 + 1];
            int kp = nt * 4 + tq;
            #pragma unroll
            for (int mf = 0; mf < 2; ++mf) {
                int row = mf * 16 + g;
                uint32_t hi, lo;
                hsplit2(fmaxf(acc[mf][j][0] + bv0, 0.0f),
                        fmaxf(acc[mf][j][1] + bv1, 0.0f), hi, lo);
                outhi[row * AST + kp] = hi; outlo[row * AST + kp] = lo;
                hsplit2(fmaxf(acc[mf][j][2] + bv0, 0.0f),
                        fmaxf(acc[mf][j][3] + bv1, 0.0f), hi, lo);
                outhi[(row + 8) * AST + kp] = hi; outlo[(row + 8) * AST + kp] = lo;
            }
        }
    }
    __syncthreads();   // out buffer visible; all in-buffer reads complete
}

// ---------- main persistent kernel ----------
// smem: 4 A arrays 55296 | S 13056 | errs 12800 | sbv 3600 | tgs 404 -> ~85.2 KB
#define SMEM_BYTES 85200

__global__ void __launch_bounds__(NT, 1)
control_solver_hmma(
    const float* __restrict__ S0, const float* __restrict__ tg,
    const float* __restrict__ dW,
    const float* __restrict__ b0, const float* __restrict__ b1,
    const float* __restrict__ b2, const float* __restrict__ b3,
    const float* __restrict__ bout, float* __restrict__ out)
{
    extern __shared__ __align__(16) char smc[];
    uint32_t* Ah0 = (uint32_t*)smc;                  // 32*108*4 each
    uint32_t* Al0 = Ah0 + MT * AST;
    uint32_t* Ah1 = Al0 + MT * AST;
    uint32_t* Al1 = Ah1 + MT * AST;
    float* S      = (float*)(Al1 + MT * AST);
    float* errs   = S + MT * SST;
    float* sbv    = errs + MT * EST;                 // 900 biases
    float* tgs    = sbv + 900;                       // 101 timegrid

    const int tid = threadIdx.x, warp = tid >> 5, lane = tid & 31;
    const int g = lane >> 2, tq = lane & 3;
    const int wn = warp;                              // 1m x 8n
    const int gm0 = blockIdx.x * MT;

    // per-lane ldmatrix base offsets
    const int lrow = (lane & 7) + ((lane >> 3) & 1) * 8;
    const int lkp  = (lane >> 4) * 4;
    const uint32_t loff = (uint32_t)((lrow * AST + lkp) * 4);
    const uint32_t a0h = smem_u32(Ah0) + loff, a0l = smem_u32(Al0) + loff;
    const uint32_t a1h = smem_u32(Ah1) + loff, a1l = smem_u32(Al1) + loff;

    for (int i = tid; i < 200; i += NT) {
        sbv[i] = b0[i]; sbv[200 + i] = b1[i]; sbv[400 + i] = b2[i]; sbv[600 + i] = b3[i];
        if (i < 100) sbv[800 + i] = bout[i];
    }
    for (int i = tid; i <= TSTEPS; i += NT) tgs[i] = tg[i];
    for (int i = tid; i < MT * DIMV; i += NT) {
        int m = i / DIMV, c = i - m * DIMV;
        S[m * SST + c] = S0[(size_t)(gm0 + m) * DIMV + c];
        errs[m * EST + c] = 0.0f;
    }
    for (int i = tid; i < MT * 8; i += NT) {         // zero pad kp 100..107 in all buffers
        int row = i >> 3, kp = 100 + (i & 7);
        Ah0[row * AST + kp] = 0; Al0[row * AST + kp] = 0;
        Ah1[row * AST + kp] = 0; Al1[row * AST + kp] = 0;
    }
    __syncthreads();
    const float h = tgs[1] - tgs[0];
    const float sqh = sqrtf(h);

    for (int t = 0; t < TSTEPS; ++t) {
        // build A0 = [t | S | 0pad] into buffer 0, kpairs 0..55
        {
            int row = tid >> 3, q = tid & 7;
            float tval = tgs[t];
            #pragma unroll
            for (int jj = 0; jj < 7; ++jj) {
                int j = q * 7 + jj, k0 = 2 * j;
                float f0 = (k0 == 0) ? tval : ((k0 <= 100) ? S[row * SST + k0 - 1] : 0.0f);
                float f1 = (k0 + 1 <= 100) ? S[row * SST + k0] : 0.0f;
                uint32_t hi, lo; hsplit2(f0, f1, hi, lo);
                Ah0[row * AST + j] = hi; Al0[row * AST + j] = lo;
            }
        }
        __syncthreads();   // A0 visible to all warps

        // prefetch dW for this step (consumed in the epilogue far below)
        float2 dwreg[2][2][2];
        #pragma unroll
        for (int j = 0; j < 2; ++j) {
            int nt = wn + 8 * j;
            if (nt < 13) {
                int n0 = nt * 8 + tq * 2;
                if (n0 < 100) {
                    #pragma unroll
                    for (int mf = 0; mf < 2; ++mf)
                        #pragma unroll
                        for (int hf = 0; hf < 2; ++hf) {
                            int m = mf * 16 + g + 8 * hf;
                            dwreg[j][mf][hf] = *(const float2*)(
                                dW + (size_t)(gm0 + m) * 10100 + (size_t)t * DIMV + n0);
                        }
                }
            }
        }

        gemm_hidden<7> (a0h, a0l, Ah1, Al1, g_Bpk + OFF_L0, sbv,       wn, g, tq);
        gemm_hidden<13>(a1h, a1l, Ah0, Al0, g_Bpk + OFF_L1, sbv + 200, wn, g, tq);
        gemm_hidden<13>(a0h, a0l, Ah1, Al1, g_Bpk + OFF_L2, sbv + 400, wn, g, tq);
        gemm_hidden<13>(a1h, a1l, Ah0, Al0, g_Bpk + OFF_L3, sbv + 600, wn, g, tq);

        // ---- output layer (reads buffer 0; 13 ksteps, npad 104) ----
        float acc[2][2][4];
        #pragma unroll
        for (int m = 0; m < 2; ++m)
            #pragma unroll
            for (int b = 0; b < 2; ++b)
                #pragma unroll
                for (int c = 0; c < 4; ++c) acc[m][b][c] = 0.0f;

        {
            const uint32_t* pb = g_Bpk + OFF_LO + (size_t)g * 16 + tq * 4;
            uint4 B[2][2];
            #pragma unroll
            for (int j = 0; j < 2; ++j) {
                int nt = wn + 8 * j;
                if (nt < 13) B[0][j] = *(const uint4*)(pb + nt * 128);
            }
            #pragma unroll
            for (int ks = 0; ks < 13; ++ks) {
                const int cb = ks & 1;
                if (ks + 1 < 13) {
                    const uint32_t* p2 = pb + (size_t)(ks + 1) * 1664;
                    #pragma unroll
                    for (int j = 0; j < 2; ++j) {
                        int nt = wn + 8 * j;
                        if (nt < 13) B[cb ^ 1][j] = *(const uint4*)(p2 + nt * 128);
                    }
                }
                uint32_t Ah[2][4], Al[2][4];
                ldsm4(Ah[0], a0h + ks * 32);
                ldsm4(Ah[1], a0h + MFOFF + ks * 32);
                ldsm4(Al[0], a0l + ks * 32);
                ldsm4(Al[1], a0l + MFOFF + ks * 32);
                #pragma unroll
                for (int j = 0; j < 2; ++j) {
                    int nt = wn + 8 * j;
                    if (nt < 13) {
                        uint32_t Bh[2] = { B[cb][j].x, B[cb][j].y };
                        uint32_t Bl[2] = { B[cb][j].z, B[cb][j].w };
                        #pragma unroll
                        for (int mf = 0; mf < 2; ++mf) {
                            mma16816(acc[mf][j], Ah[mf], Bh);
                            mma16816(acc[mf][j], Ah[mf], Bl);
                            mma16816(acc[mf][j], Al[mf], Bh);
                        }
                    }
                }
            }
        }
        // no sync needed: epilogue touches only S/errs/out (disjoint from A reads)

        // ---- SDE epilogue: u = D + bout; err in smem; S update; out only at end ----
        #pragma unroll
        for (int j = 0; j < 2; ++j) {
            int nt = wn + 8 * j;
            if (nt < 13) {
                int n0 = nt * 8 + tq * 2;
                if (n0 < 100) {
                    float bv0 = sbv[800 + n0], bv1 = sbv[800 + n0 + 1];
                    #pragma unroll
                    for (int mf = 0; mf < 2; ++mf)
                        #pragma unroll
                        for (int hf = 0; hf < 2; ++hf) {
                            int m = mf * 16 + g + 8 * hf;
                            float u0 = acc[mf][j][2 * hf]     + bv0;
                            float u1 = acc[mf][j][2 * hf + 1] + bv1;
                            float2 dw = dwreg[j][mf][hf];
                            float s0 = S[m * SST + n0]     + u0 * (h + sqh * dw.x);
                            float s1 = S[m * SST + n0 + 1] + u1 * (h + sqh * dw.y);
                            float e0 = errs[m * EST + n0]     + u0 * u0 * h;
                            float e1 = errs[m * EST + n0 + 1] + u1 * u1 * h;
                            if (t == TSTEPS - 1) {
                                float2* op = (float2*)(out + (size_t)(gm0 + m) * DIMV + n0);
                                *op = make_float2(e0 + s0 * s0, e1 + s1 * s1);
                            } else {
                                S[m * SST + n0] = s0; S[m * SST + n0 + 1] = s1;
                                errs[m * EST + n0] = e0; errs[m * EST + n0 + 1] = e1;
                            }
                        }
                }
            }
        }
        __syncthreads();   // S stable before next build_A0 (which rewrites buffer 0)
    }
}

extern "C" void kernel_launch(void* const* d_in, const int* in_sizes, int n_in,
                              void* d_out, int out_size) {
    const float* S0   = (const float*)d_in[0];
    const float* tg   = (const float*)d_in[1];
    const float* dW   = (const float*)d_in[2];
    const float* W0   = (const float*)d_in[3];
    const float* b0   = (const float*)d_in[4];
    const float* W1   = (const float*)d_in[5];
    const float* b1   = (const float*)d_in[6];
    const float* W2   = (const float*)d_in[7];
    const float* b2   = (const float*)d_in[8];
    const float* W3   = (const float*)d_in[9];
    const float* b3   = (const float*)d_in[10];
    const float* Wout = (const float*)d_in[11];
    const float* bout = (const float*)d_in[12];
    float* out = (float*)d_out;

    pack_b<<<(7  * 200 * 8 + 255) / 256, 256>>>(W0,   101, 200, 200, 7,  OFF_L0);
    pack_b<<<(13 * 200 * 8 + 255) / 256, 256>>>(W1,   200, 200, 200, 13, OFF_L1);
    pack_b<<<(13 * 200 * 8 + 255) / 256, 256>>>(W2,   200, 200, 200, 13, OFF_L2);
    pack_b<<<(13 * 200 * 8 + 255) / 256, 256>>>(W3,   200, 200, 200, 13, OFF_L3);
    pack_b<<<(13 * 104 * 8 + 255) / 256, 256>>>(Wout, 200, 100, 104, 13, OFF_LO);

    cudaFuncSetAttribute(control_solver_hmma,
                         cudaFuncAttributeMaxDynamicSharedMemorySize, SMEM_BYTES);
    control_solver_hmma<<<4096 / MT, NT, SMEM_BYTES>>>(
        S0, tg, dW, b0, b1, b2, b3, bout, out);
}

// round 16
// speedup vs baseline: 1.4759x; 1.0217x over previous
#include <cuda_runtime.h>
#include <cuda_fp16.h>
#include <math.h>
#include <stdint.h>

#define DIMV   100
#define TSTEPS 100
#define NT     256
#define MT     32          // rows per CTA -> 128 CTAs
#define AST    108         // A row stride in u32 (conflict-free for LDSM phases)
#define SST    102         // S row stride in floats
#define EST    100         // err row stride in floats
#define MFOFF  (16*AST*4)  // byte offset of mf=1 tile

// weight pool: per layer, per k16-step: [npad][16] u32:
//   slot = n*16 + tq*4 + {0:hi(kp=tq),1:hi(kp=tq+4),2:lo(kp=tq),3:lo(kp=tq+4)}
#define OFF_L0 0
#define OFF_L1 22400
#define OFF_L2 64000
#define OFF_L3 105600
#define OFF_LO 147200
__device__ __align__(16) uint32_t g_Bpk[168832];

// ---------- helpers ----------
__device__ __forceinline__ uint32_t smem_u32(const void* p) {
    uint32_t a;
    asm("{ .reg .u64 t; cvta.to.shared.u64 t, %1; cvt.u32.u64 %0, t; }" : "=r"(a) : "l"(p));
    return a;
}
__device__ __forceinline__ void hsplit2(float f0, float f1, uint32_t& hi, uint32_t& lo) {
    __half h0 = __float2half_rn(f0), h1 = __float2half_rn(f1);
    __half l0 = __float2half_rn(f0 - __half2float(h0));
    __half l1 = __float2half_rn(f1 - __half2float(h1));
    hi = ((uint32_t)__half_as_ushort(h1) << 16) | __half_as_ushort(h0);
    lo = ((uint32_t)__half_as_ushort(l1) << 16) | __half_as_ushort(l0);
}
__device__ __forceinline__ void mma16816(float* c, const uint32_t* a, const uint32_t* b) {
    asm volatile("mma.sync.aligned.m16n8k16.row.col.f32.f16.f16.f32 "
        "{%0,%1,%2,%3}, {%4,%5,%6,%7}, {%8,%9}, {%0,%1,%2,%3};"
        : "+f"(c[0]), "+f"(c[1]), "+f"(c[2]), "+f"(c[3])
        : "r"(a[0]), "r"(a[1]), "r"(a[2]), "r"(a[3]), "r"(b[0]), "r"(b[1]));
}
__device__ __forceinline__ void ldsm4(uint32_t* r, uint32_t addr) {
    asm volatile("ldmatrix.sync.aligned.m8n8.x4.shared.b16 {%0,%1,%2,%3}, [%4];"
        : "=r"(r[0]), "=r"(r[1]), "=r"(r[2]), "=r"(r[3]) : "r"(addr));
}

// ---------- weight pack: all 5 layers in ONE launch ----------
__device__ __forceinline__ void pack_one(const float* __restrict__ W,
                                         int Kr, int Nr, int npad, int off, int lidx) {
    int ks = lidx / (npad * 8), r = lidx - ks * npad * 8, n = r >> 3, kp = r & 7;
    int k0 = ks * 16 + kp * 2, k1 = k0 + 1;
    float v0 = (k0 < Kr && n < Nr) ? W[(size_t)k0 * Nr + n] : 0.0f;
    float v1 = (k1 < Kr && n < Nr) ? W[(size_t)k1 * Nr + n] : 0.0f;
    uint32_t hi, lo; hsplit2(v0, v1, hi, lo);
    int tq = kp & 3, hs = kp >> 2;
    int b = off + ks * npad * 16 + n * 16 + tq * 4;
    g_Bpk[b + hs]     = hi;
    g_Bpk[b + 2 + hs] = lo;
}
__global__ void pack_all(const float* __restrict__ W0, const float* __restrict__ W1,
                         const float* __restrict__ W2, const float* __restrict__ W3,
                         const float* __restrict__ Wout) {
    int idx = blockIdx.x * blockDim.x + threadIdx.x;
    if      (idx < 11200) pack_one(W0,   101, 200, 200, OFF_L0, idx);
    else if (idx < 32000) pack_one(W1,   200, 200, 200, OFF_L1, idx - 11200);
    else if (idx < 52800) pack_one(W2,   200, 200, 200, OFF_L2, idx - 32000);
    else if (idx < 73600) pack_one(W3,   200, 200, 200, OFF_L3, idx - 52800);
    else if (idx < 84416) pack_one(Wout, 200, 100, 104, OFF_LO, idx - 73600);
}

// ---------- hidden-layer GEMM + epilogue (1m x 8n grid, mf=2, 32 rows/warp) ----------
// Consumes B0 (first-kstep fragments, preloaded), and refills B0 from poolnext
// (next layer's first kstep) BEFORE the epilogue+sync, hiding that latency.
template<int KS, int NEXTLIM>
__device__ __forceinline__ void gemm_hidden(
    uint32_t inhi, uint32_t inlo, uint32_t* outhi, uint32_t* outlo,
    const uint32_t* pool, const uint32_t* poolnext, uint4 (&B0)[4],
    const float* bias, int wn, int g, int tq)
{
    float acc[2][4][4];
    #pragma unroll
    for (int m = 0; m < 2; ++m)
        #pragma unroll
        for (int b = 0; b < 4; ++b)
            #pragma unroll
            for (int c = 0; c < 4; ++c) acc[m][b][c] = 0.0f;

    const uint32_t* pb = pool + (size_t)g * 16 + tq * 4;
    uint4 B[2][4];
    #pragma unroll
    for (int j = 0; j < 4; ++j) B[0][j] = B0[j];

    #pragma unroll
    for (int ks = 0; ks < KS; ++ks) {
        const int cb = ks & 1;
        if (ks + 1 < KS) {
            const uint32_t* p2 = pb + (size_t)(ks + 1) * 3200;
            #pragma unroll
            for (int j = 0; j < 4; ++j) {
                int nt = wn + 8 * j;
                if (nt < 25) B[cb ^ 1][j] = *(const uint4*)(p2 + nt * 128);
            }
        }
        uint32_t Ah[2][4], Al[2][4];
        ldsm4(Ah[0], inhi + ks * 32);
        ldsm4(Ah[1], inhi + MFOFF + ks * 32);
        ldsm4(Al[0], inlo + ks * 32);
        ldsm4(Al[1], inlo + MFOFF + ks * 32);
        #pragma unroll
        for (int j = 0; j < 4; ++j) {
            int nt = wn + 8 * j;
            if (nt < 25) {
                uint32_t Bh[2] = { B[cb][j].x, B[cb][j].y };
                uint32_t Bl[2] = { B[cb][j].z, B[cb][j].w };
                #pragma unroll
                for (int mf = 0; mf < 2; ++mf) {
                    mma16816(acc[mf][j], Ah[mf], Bh);
                    mma16816(acc[mf][j], Ah[mf], Bl);
                    mma16816(acc[mf][j], Al[mf], Bh);
                }
            }
        }
    }

    // prefetch NEXT layer's first-kstep B fragments (latency hides under epilogue+sync)
    {
        const uint32_t* pbn = poolnext + (size_t)g * 16 + tq * 4;
        #pragma unroll
        for (int j = 0; j < 4; ++j) {
            int nt = wn + 8 * j;
            if (nt < NEXTLIM) B0[j] = *(const uint4*)(pbn + nt * 128);
        }
    }

    #pragma unroll
    for (int j = 0; j < 4; ++j) {
        int nt = wn + 8 * j;
        if (nt < 25) {
            int n0 = nt * 8 + tq * 2;
            float bv0 = bias[n0], bv1 = bias[n0 + 1];
            int kp = nt * 4 + tq;
            #pragma unroll
            for (int mf = 0; mf < 2; ++mf) {
                int row = mf * 16 + g;
                uint32_t hi, lo;
                hsplit2(fmaxf(acc[mf][j][0] + bv0, 0.0f),
                        fmaxf(acc[mf][j][1] + bv1, 0.0f), hi, lo);
                outhi[row * AST + kp] = hi; outlo[row * AST + kp] = lo;
                hsplit2(fmaxf(acc[mf][j][2] + bv0, 0.0f),
                        fmaxf(acc[mf][j][3] + bv1, 0.0f), hi, lo);
                outhi[(row + 8) * AST + kp] = hi; outlo[(row + 8) * AST + kp] = lo;
            }
        }
    }
    __syncthreads();   // out buffer visible; all in-buffer reads complete
}

// ---------- main persistent kernel ----------
#define SMEM_BYTES 85200

__global__ void __launch_bounds__(NT, 1)
control_solver_hmma(
    const float* __restrict__ S0, const float* __restrict__ tg,
    const float* __restrict__ dW,
    const float* __restrict__ b0, const float* __restrict__ b1,
    const float* __restrict__ b2, const float* __restrict__ b3,
    const float* __restrict__ bout, float* __restrict__ out)
{
    extern __shared__ __align__(16) char smc[];
    uint32_t* Ah0 = (uint32_t*)smc;                  // 32*108*4 each
    uint32_t* Al0 = Ah0 + MT * AST;
    uint32_t* Ah1 = Al0 + MT * AST;
    uint32_t* Al1 = Ah1 + MT * AST;
    float* S      = (float*)(Al1 + MT * AST);
    float* errs   = S + MT * SST;
    float* sbv    = errs + MT * EST;                 // 900 biases
    float* tgs    = sbv + 900;                       // 101 timegrid

    const int tid = threadIdx.x, warp = tid >> 5, lane = tid & 31;
    const int g = lane >> 2, tq = lane & 3;
    const int wn = warp;                              // 1m x 8n
    const int gm0 = blockIdx.x * MT;

    const int lrow = (lane & 7) + ((lane >> 3) & 1) * 8;
    const int lkp  = (lane >> 4) * 4;
    const uint32_t loff = (uint32_t)((lrow * AST + lkp) * 4);
    const uint32_t a0h = smem_u32(Ah0) + loff, a0l = smem_u32(Al0) + loff;
    const uint32_t a1h = smem_u32(Ah1) + loff, a1l = smem_u32(Al1) + loff;

    for (int i = tid; i < 200; i += NT) {
        sbv[i] = b0[i]; sbv[200 + i] = b1[i]; sbv[400 + i] = b2[i]; sbv[600 + i] = b3[i];
        if (i < 100) sbv[800 + i] = bout[i];
    }
    for (int i = tid; i <= TSTEPS; i += NT) tgs[i] = tg[i];
    for (int i = tid; i < MT * DIMV; i += NT) {
        int m = i / DIMV, c = i - m * DIMV;
        S[m * SST + c] = S0[(size_t)(gm0 + m) * DIMV + c];
        errs[m * EST + c] = 0.0f;
    }
    for (int i = tid; i < MT * 8; i += NT) {
        int row = i >> 3, kp = 100 + (i & 7);
        Ah0[row * AST + kp] = 0; Al0[row * AST + kp] = 0;
        Ah1[row * AST + kp] = 0; Al1[row * AST + kp] = 0;
    }
    __syncthreads();
    const float h = tgs[1] - tgs[0];
    const float sqh = sqrtf(h);

    // prime B0 with layer 0's first-kstep fragments
    uint4 B0[4];
    {
        const uint32_t* pbn = g_Bpk + OFF_L0 + (size_t)g * 16 + tq * 4;
        #pragma unroll
        for (int j = 0; j < 4; ++j) {
            int nt = wn + 8 * j;
            if (nt < 25) B0[j] = *(const uint4*)(pbn + nt * 128);
        }
    }

    for (int t = 0; t < TSTEPS; ++t) {
        // build A0 = [t | S | 0pad] into buffer 0, kpairs 0..55
        {
            int row = tid >> 3, q = tid & 7;
            float tval = tgs[t];
            #pragma unroll
            for (int jj = 0; jj < 7; ++jj) {
                int j = q * 7 + jj, k0 = 2 * j;
                float f0 = (k0 == 0) ? tval : ((k0 <= 100) ? S[row * SST + k0 - 1] : 0.0f);
                float f1 = (k0 + 1 <= 100) ? S[row * SST + k0] : 0.0f;
                uint32_t hi, lo; hsplit2(f0, f1, hi, lo);
                Ah0[row * AST + j] = hi; Al0[row * AST + j] = lo;
            }
        }
        __syncthreads();   // A0 visible to all warps

        // prefetch dW for this step (consumed in the epilogue far below)
        float2 dwreg[2][2][2];
        #pragma unroll
        for (int j = 0; j < 2; ++j) {
            int nt = wn + 8 * j;
            if (nt < 13) {
                int n0 = nt * 8 + tq * 2;
                if (n0 < 100) {
                    #pragma unroll
                    for (int mf = 0; mf < 2; ++mf)
                        #pragma unroll
                        for (int hf = 0; hf < 2; ++hf) {
                            int m = mf * 16 + g + 8 * hf;
                            dwreg[j][mf][hf] = *(const float2*)(
                                dW + (size_t)(gm0 + m) * 10100 + (size_t)t * DIMV + n0);
                        }
                }
            }
        }

        gemm_hidden<7, 25>(a0h, a0l, Ah1, Al1, g_Bpk + OFF_L0, g_Bpk + OFF_L1, B0,
                           sbv,       wn, g, tq);
        gemm_hidden<13, 25>(a1h, a1l, Ah0, Al0, g_Bpk + OFF_L1, g_Bpk + OFF_L2, B0,
                           sbv + 200, wn, g, tq);
        gemm_hidden<13, 25>(a0h, a0l, Ah1, Al1, g_Bpk + OFF_L2, g_Bpk + OFF_L3, B0,
                           sbv + 400, wn, g, tq);
        gemm_hidden<13, 13>(a1h, a1l, Ah0, Al0, g_Bpk + OFF_L3, g_Bpk + OFF_LO, B0,
                           sbv + 600, wn, g, tq);

        // ---- output layer (reads buffer 0; 13 ksteps, npad 104) ----
        float acc[2][2][4];
        #pragma unroll
        for (int m = 0; m < 2; ++m)
            #pragma unroll
            for (int b = 0; b < 2; ++b)
                #pragma unroll
                for (int c = 0; c < 4; ++c) acc[m][b][c] = 0.0f;

        {
            const uint32_t* pb = g_Bpk + OFF_LO + (size_t)g * 16 + tq * 4;
            uint4 B[2][2];
            #pragma unroll
            for (int j = 0; j < 2; ++j) B[0][j] = B0[j];
            #pragma unroll
            for (int ks = 0; ks < 13; ++ks) {
                const int cb = ks & 1;
                if (ks + 1 < 13) {
                    const uint32_t* p2 = pb + (size_t)(ks + 1) * 1664;
                    #pragma unroll
                    for (int j = 0; j < 2; ++j) {
                        int nt = wn + 8 * j;
                        if (nt < 13) B[cb ^ 1][j] = *(const uint4*)(p2 + nt * 128);
                    }
                }
                uint32_t Ah[2][4], Al[2][4];
                ldsm4(Ah[0], a0h + ks * 32);
                ldsm4(Ah[1], a0h + MFOFF + ks * 32);
                ldsm4(Al[0], a0l + ks * 32);
                ldsm4(Al[1], a0l + MFOFF + ks * 32);
                #pragma unroll
                for (int j = 0; j < 2; ++j) {
                    int nt = wn + 8 * j;
                    if (nt < 13) {
                        uint32_t Bh[2] = { B[cb][j].x, B[cb][j].y };
                        uint32_t Bl[2] = { B[cb][j].z, B[cb][j].w };
                        #pragma unroll
                        for (int mf = 0; mf < 2; ++mf) {
                            mma16816(acc[mf][j], Ah[mf], Bh);
                            mma16816(acc[mf][j], Ah[mf], Bl);
                            mma16816(acc[mf][j], Al[mf], Bh);
                        }
                    }
                }
            }
            // prefetch next step's L0 first-kstep B (hides under SDE epilogue + sync)
            const uint32_t* pbn = g_Bpk + OFF_L0 + (size_t)g * 16 + tq * 4;
            #pragma unroll
            for (int j = 0; j < 4; ++j) {
                int nt = wn + 8 * j;
                if (nt < 25) B0[j] = *(const uint4*)(pbn + nt * 128);
            }
        }
        // no sync needed: epilogue touches only S/errs/out (disjoint from A reads)

        // ---- SDE epilogue: u = D + bout; err in smem; S update; out only at end ----
        #pragma unroll
        for (int j = 0; j < 2; ++j) {
            int nt = wn + 8 * j;
            if (nt < 13) {
                int n0 = nt * 8 + tq * 2;
                if (n0 < 100) {
                    float bv0 = sbv[800 + n0], bv1 = sbv[800 + n0 + 1];
                    #pragma unroll
                    for (int mf = 0; mf < 2; ++mf)
                        #pragma unroll
                        for (int hf = 0; hf < 2; ++hf) {
                            int m = mf * 16 + g + 8 * hf;
                            float u0 = acc[mf][j][2 * hf]     + bv0;
                            float u1 = acc[mf][j][2 * hf + 1] + bv1;
                            float2 dw = dwreg[j][mf][hf];
                            float s0 = S[m * SST + n0]     + u0 * (h + sqh * dw.x);
                            float s1 = S[m * SST + n0 + 1] + u1 * (h + sqh * dw.y);
                            float e0 = errs[m * EST + n0]     + u0 * u0 * h;
                            float e1 = errs[m * EST + n0 + 1] + u1 * u1 * h;
                            if (t == TSTEPS - 1) {
                                float2* op = (float2*)(out + (size_t)(gm0 + m) * DIMV + n0);
                                *op = make_float2(e0 + s0 * s0, e1 + s1 * s1);
                            } else {
                                S[m * SST + n0] = s0; S[m * SST + n0 + 1] = s1;
                                errs[m * EST + n0] = e0; errs[m * EST + n0 + 1] = e1;
                            }
                        }
                }
            }
        }
        __syncthreads();   // S stable before next build_A0 (which rewrites buffer 0)
    }
}

extern "C" void kernel_launch(void* const* d_in, const int* in_sizes, int n_in,
                              void* d_out, int out_size) {
    const float* S0   = (const float*)d_in[0];
    const float* tg   = (const float*)d_in[1];
    const float* dW   = (const float*)d_in[2];
    const float* W0   = (const float*)d_in[3];
    const float* b0   = (const float*)d_in[4];
    const float* W1   = (const float*)d_in[5];
    const float* b1   = (const float*)d_in[6];
    const float* W2   = (const float*)d_in[7];
    const float* b2   = (const float*)d_in[8];
    const float* W3   = (const float*)d_in[9];
    const float* b3   = (const float*)d_in[10];
    const float* Wout = (const float*)d_in[11];
    const float* bout = (const float*)d_in[12];
    float* out = (float*)d_out;

    pack_all<<<(84416 + 255) / 256, 256>>>(W0, W1, W2, W3, Wout);

    cudaFuncSetAttribute(control_solver_hmma,
                         cudaFuncAttributeMaxDynamicSharedMemorySize, SMEM_BYTES);
    control_solver_hmma<<<4096 / MT, NT, SMEM_BYTES>>>(
        S0, tg, dW, b0, b1, b2, b3, bout, out);
}

// round 17
// speedup vs baseline: 1.5639x; 1.0596x over previous
#include <cuda_runtime.h>
#include <cuda_fp16.h>
#include <math.h>
#include <stdint.h>

#define DIMV   100
#define TSTEPS 100
#define NT     256
#define MT     16          // rows per CTA -> 256 CTAs, 2 CTAs/SM
#define AST    108         // A row stride in u32 (conflict-free for LDSM phases)
#define SST    102
#define EST    100

// weight pool: per layer, per k16-step: [npad][16] u32
#define OFF_L0 0
#define OFF_L1 22400
#define OFF_L2 64000
#define OFF_L3 105600
#define OFF_LO 147200
__device__ __align__(16) uint32_t g_Bpk[168832];

// ---------- helpers ----------
__device__ __forceinline__ uint32_t smem_u32(const void* p) {
    uint32_t a;
    asm("{ .reg .u64 t; cvta.to.shared.u64 t, %1; cvt.u32.u64 %0, t; }" : "=r"(a) : "l"(p));
    return a;
}
__device__ __forceinline__ void hsplit2(float f0, float f1, uint32_t& hi, uint32_t& lo) {
    __half h0 = __float2half_rn(f0), h1 = __float2half_rn(f1);
    __half l0 = __float2half_rn(f0 - __half2float(h0));
    __half l1 = __float2half_rn(f1 - __half2float(h1));
    hi = ((uint32_t)__half_as_ushort(h1) << 16) | __half_as_ushort(h0);
    lo = ((uint32_t)__half_as_ushort(l1) << 16) | __half_as_ushort(l0);
}
__device__ __forceinline__ void mma16816(float* c, const uint32_t* a, const uint32_t* b) {
    asm volatile("mma.sync.aligned.m16n8k16.row.col.f32.f16.f16.f32 "
        "{%0,%1,%2,%3}, {%4,%5,%6,%7}, {%8,%9}, {%0,%1,%2,%3};"
        : "+f"(c[0]), "+f"(c[1]), "+f"(c[2]), "+f"(c[3])
        : "r"(a[0]), "r"(a[1]), "r"(a[2]), "r"(a[3]), "r"(b[0]), "r"(b[1]));
}
__device__ __forceinline__ void ldsm4(uint32_t* r, uint32_t addr) {
    asm volatile("ldmatrix.sync.aligned.m8n8.x4.shared.b16 {%0,%1,%2,%3}, [%4];"
        : "=r"(r[0]), "=r"(r[1]), "=r"(r[2]), "=r"(r[3]) : "r"(addr));
}

// ---------- weight pack (single launch) ----------
__device__ __forceinline__ void pack_one(const float* __restrict__ W,
                                         int Kr, int Nr, int npad, int off, int lidx) {
    int ks = lidx / (npad * 8), r = lidx - ks * npad * 8, n = r >> 3, kp = r & 7;
    int k0 = ks * 16 + kp * 2, k1 = k0 + 1;
    float v0 = (k0 < Kr && n < Nr) ? W[(size_t)k0 * Nr + n] : 0.0f;
    float v1 = (k1 < Kr && n < Nr) ? W[(size_t)k1 * Nr + n] : 0.0f;
    uint32_t hi, lo; hsplit2(v0, v1, hi, lo);
    int tq = kp & 3, hs = kp >> 2;
    int b = off + ks * npad * 16 + n * 16 + tq * 4;
    g_Bpk[b + hs]     = hi;
    g_Bpk[b + 2 + hs] = lo;
}
__global__ void pack_all(const float* __restrict__ W0, const float* __restrict__ W1,
                         const float* __restrict__ W2, const float* __restrict__ W3,
                         const float* __restrict__ Wout) {
    int idx = blockIdx.x * blockDim.x + threadIdx.x;
    if      (idx < 11200) pack_one(W0,   101, 200, 200, OFF_L0, idx);
    else if (idx < 32000) pack_one(W1,   200, 200, 200, OFF_L1, idx - 11200);
    else if (idx < 52800) pack_one(W2,   200, 200, 200, OFF_L2, idx - 32000);
    else if (idx < 73600) pack_one(W3,   200, 200, 200, OFF_L3, idx - 52800);
    else if (idx < 84416) pack_one(Wout, 200, 100, 104, OFF_LO, idx - 73600);
}

// ---------- hidden-layer GEMM + epilogue (1m x 8n grid, 16 rows/warp) ----------
template<int KS, int NEXTLIM>
__device__ __forceinline__ void gemm_hidden(
    uint32_t inhi, uint32_t inlo, uint32_t* outhi, uint32_t* outlo,
    const uint32_t* pool, const uint32_t* poolnext, uint4 (&B0)[4],
    const float* bias, int wn, int g, int tq)
{
    float acc[4][4];
    #pragma unroll
    for (int b = 0; b < 4; ++b)
        #pragma unroll
        for (int c = 0; c < 4; ++c) acc[b][c] = 0.0f;

    const uint32_t* pb = pool + (size_t)g * 16 + tq * 4;
    uint4 B[2][4];
    #pragma unroll
    for (int j = 0; j < 4; ++j) B[0][j] = B0[j];

    #pragma unroll
    for (int ks = 0; ks < KS; ++ks) {
        const int cb = ks & 1;
        if (ks + 1 < KS) {
            const uint32_t* p2 = pb + (size_t)(ks + 1) * 3200;
            #pragma unroll
            for (int j = 0; j < 4; ++j) {
                int nt = wn + 8 * j;
                if (nt < 25) B[cb ^ 1][j] = *(const uint4*)(p2 + nt * 128);
            }
        }
        uint32_t Ah[4], Al[4];
        ldsm4(Ah, inhi + ks * 32);
        ldsm4(Al, inlo + ks * 32);
        // pass-major order: 4 independent MMAs between dependent ones
        #pragma unroll
        for (int p = 0; p < 3; ++p) {
            #pragma unroll
            for (int j = 0; j < 4; ++j) {
                int nt = wn + 8 * j;
                if (nt < 25) {
                    uint32_t Bf[2];
                    if (p == 1) { Bf[0] = B[cb][j].z; Bf[1] = B[cb][j].w; }
                    else        { Bf[0] = B[cb][j].x; Bf[1] = B[cb][j].y; }
                    mma16816(acc[j], (p == 2) ? Al : Ah, Bf);
                }
            }
        }
    }

    // prefetch NEXT layer's first-kstep B (hides under epilogue + sync)
    {
        const uint32_t* pbn = poolnext + (size_t)g * 16 + tq * 4;
        #pragma unroll
        for (int j = 0; j < 4; ++j) {
            int nt = wn + 8 * j;
            if (nt < NEXTLIM) B0[j] = *(const uint4*)(pbn + nt * 128);
        }
    }

    #pragma unroll
    for (int j = 0; j < 4; ++j) {
        int nt = wn + 8 * j;
        if (nt < 25) {
            int n0 = nt * 8 + tq * 2;
            float bv0 = bias[n0], bv1 = bias[n0 + 1];
            int kp = nt * 4 + tq;
            uint32_t hi, lo;
            hsplit2(fmaxf(acc[j][0] + bv0, 0.0f), fmaxf(acc[j][1] + bv1, 0.0f), hi, lo);
            outhi[g * AST + kp] = hi; outlo[g * AST + kp] = lo;
            hsplit2(fmaxf(acc[j][2] + bv0, 0.0f), fmaxf(acc[j][3] + bv1, 0.0f), hi, lo);
            outhi[(g + 8) * AST + kp] = hi; outlo[(g + 8) * AST + kp] = lo;
        }
    }
    __syncthreads();
}

// ---------- main persistent kernel ----------
// smem: 4 A arrays 27648 | S 6528 | errs 6400 | sbv 3600 | tgs 404 -> ~44.6 KB/CTA
#define SMEM_BYTES 44800

__global__ void __launch_bounds__(NT, 2)
control_solver_hmma(
    const float* __restrict__ S0, const float* __restrict__ tg,
    const float* __restrict__ dW,
    const float* __restrict__ b0, const float* __restrict__ b1,
    const float* __restrict__ b2, const float* __restrict__ b3,
    const float* __restrict__ bout, float* __restrict__ out)
{
    extern __shared__ __align__(16) char smc[];
    uint32_t* Ah0 = (uint32_t*)smc;                  // 16*108*4 each
    uint32_t* Al0 = Ah0 + MT * AST;
    uint32_t* Ah1 = Al0 + MT * AST;
    uint32_t* Al1 = Ah1 + MT * AST;
    float* S      = (float*)(Al1 + MT * AST);
    float* errs   = S + MT * SST;
    float* sbv    = errs + MT * EST;
    float* tgs    = sbv + 900;

    const int tid = threadIdx.x, warp = tid >> 5, lane = tid & 31;
    const int g = lane >> 2, tq = lane & 3;
    const int wn = warp;
    const int gm0 = blockIdx.x * MT;

    const int lrow = (lane & 7) + ((lane >> 3) & 1) * 8;
    const int lkp  = (lane >> 4) * 4;
    const uint32_t loff = (uint32_t)((lrow * AST + lkp) * 4);
    const uint32_t a0h = smem_u32(Ah0) + loff, a0l = smem_u32(Al0) + loff;
    const uint32_t a1h = smem_u32(Ah1) + loff, a1l = smem_u32(Al1) + loff;

    for (int i = tid; i < 200; i += NT) {
        sbv[i] = b0[i]; sbv[200 + i] = b1[i]; sbv[400 + i] = b2[i]; sbv[600 + i] = b3[i];
        if (i < 100) sbv[800 + i] = bout[i];
    }
    for (int i = tid; i <= TSTEPS; i += NT) tgs[i] = tg[i];
    for (int i = tid; i < MT * DIMV; i += NT) {
        int m = i / DIMV, c = i - m * DIMV;
        S[m * SST + c] = S0[(size_t)(gm0 + m) * DIMV + c];
        errs[m * EST + c] = 0.0f;
    }
    for (int i = tid; i < MT * 8; i += NT) {
        int row = i >> 3, kp = 100 + (i & 7);
        Ah0[row * AST + kp] = 0; Al0[row * AST + kp] = 0;
        Ah1[row * AST + kp] = 0; Al1[row * AST + kp] = 0;
    }
    __syncthreads();
    const float h = tgs[1] - tgs[0];
    const float sqh = sqrtf(h);

    uint4 B0[4];
    {
        const uint32_t* pbn = g_Bpk + OFF_L0 + (size_t)g * 16 + tq * 4;
        #pragma unroll
        for (int j = 0; j < 4; ++j) {
            int nt = wn + 8 * j;
            if (nt < 25) B0[j] = *(const uint4*)(pbn + nt * 128);
        }
    }

    for (int t = 0; t < TSTEPS; ++t) {
        // build A0 = [t | S | 0pad] into buffer 0, kpairs 0..55
        {
            int row = tid >> 4, q = tid & 15;
            float tval = tgs[t];
            #pragma unroll
            for (int jj = 0; jj < 4; ++jj) {
                int j = q * 4 + jj;
                if (j < 56) {
                    int k0 = 2 * j;
                    float f0 = (k0 == 0) ? tval : ((k0 <= 100) ? S[row * SST + k0 - 1] : 0.0f);
                    float f1 = (k0 + 1 <= 100) ? S[row * SST + k0] : 0.0f;
                    uint32_t hi, lo; hsplit2(f0, f1, hi, lo);
                    Ah0[row * AST + j] = hi; Al0[row * AST + j] = lo;
                }
            }
        }
        __syncthreads();

        // prefetch dW for this step
        float2 dwreg[2][2];
        #pragma unroll
        for (int j = 0; j < 2; ++j) {
            int nt = wn + 8 * j;
            if (nt < 13) {
                int n0 = nt * 8 + tq * 2;
                if (n0 < 100) {
                    #pragma unroll
                    for (int hf = 0; hf < 2; ++hf) {
                        int m = g + 8 * hf;
                        dwreg[j][hf] = *(const float2*)(
                            dW + (size_t)(gm0 + m) * 10100 + (size_t)t * DIMV + n0);
                    }
                }
            }
        }

        gemm_hidden<7, 25>(a0h, a0l, Ah1, Al1, g_Bpk + OFF_L0, g_Bpk + OFF_L1, B0,
                           sbv,       wn, g, tq);
        gemm_hidden<13, 25>(a1h, a1l, Ah0, Al0, g_Bpk + OFF_L1, g_Bpk + OFF_L2, B0,
                           sbv + 200, wn, g, tq);
        gemm_hidden<13, 25>(a0h, a0l, Ah1, Al1, g_Bpk + OFF_L2, g_Bpk + OFF_L3, B0,
                           sbv + 400, wn, g, tq);
        gemm_hidden<13, 13>(a1h, a1l, Ah0, Al0, g_Bpk + OFF_L3, g_Bpk + OFF_LO, B0,
                           sbv + 600, wn, g, tq);

        // ---- output layer (reads buffer 0; 13 ksteps, npad 104) ----
        float acc[2][4];
        #pragma unroll
        for (int b = 0; b < 2; ++b)
            #pragma unroll
            for (int c = 0; c < 4; ++c) acc[b][c] = 0.0f;

        {
            const uint32_t* pb = g_Bpk + OFF_LO + (size_t)g * 16 + tq * 4;
            uint4 B[2][2];
            #pragma unroll
            for (int j = 0; j < 2; ++j) B[0][j] = B0[j];
            #pragma unroll
            for (int ks = 0; ks < 13; ++ks) {
                const int cb = ks & 1;
                if (ks + 1 < 13) {
                    const uint32_t* p2 = pb + (size_t)(ks + 1) * 1664;
                    #pragma unroll
                    for (int j = 0; j < 2; ++j) {
                        int nt = wn + 8 * j;
                        if (nt < 13) B[cb ^ 1][j] = *(const uint4*)(p2 + nt * 128);
                    }
                }
                uint32_t Ah[4], Al[4];
                ldsm4(Ah, a0h + ks * 32);
                ldsm4(Al, a0l + ks * 32);
                #pragma unroll
                for (int p = 0; p < 3; ++p) {
                    #pragma unroll
                    for (int j = 0; j < 2; ++j) {
                        int nt = wn + 8 * j;
                        if (nt < 13) {
                            uint32_t Bf[2];
                            if (p == 1) { Bf[0] = B[cb][j].z; Bf[1] = B[cb][j].w; }
                            else        { Bf[0] = B[cb][j].x; Bf[1] = B[cb][j].y; }
                            mma16816(acc[j], (p == 2) ? Al : Ah, Bf);
                        }
                    }
                }
            }
            // prefetch next step's L0 first-kstep B
            const uint32_t* pbn = g_Bpk + OFF_L0 + (size_t)g * 16 + tq * 4;
            #pragma unroll
            for (int j = 0; j < 4; ++j) {
                int nt = wn + 8 * j;
                if (nt < 25) B0[j] = *(const uint4*)(pbn + nt * 128);
            }
        }

        // ---- SDE epilogue ----
        #pragma unroll
        for (int j = 0; j < 2; ++j) {
            int nt = wn + 8 * j;
            if (nt < 13) {
                int n0 = nt * 8 + tq * 2;
                if (n0 < 100) {
                    float bv0 = sbv[800 + n0], bv1 = sbv[800 + n0 + 1];
                    #pragma unroll
                    for (int hf = 0; hf < 2; ++hf) {
                        int m = g + 8 * hf;
                        float u0 = acc[j][2 * hf]     + bv0;
                        float u1 = acc[j][2 * hf + 1] + bv1;
                        float2 dw = dwreg[j][hf];
                        float s0 = S[m * SST + n0]     + u0 * (h + sqh * dw.x);
                        float s1 = S[m * SST + n0 + 1] + u1 * (h + sqh * dw.y);
                        float e0 = errs[m * EST + n0]     + u0 * u0 * h;
                        float e1 = errs[m * EST + n0 + 1] + u1 * u1 * h;
                        if (t == TSTEPS - 1) {
                            float2* op = (float2*)(out + (size_t)(gm0 + m) * DIMV + n0);
                            *op = make_float2(e0 + s0 * s0, e1 + s1 * s1);
                        } else {
                            S[m * SST + n0] = s0; S[m * SST + n0 + 1] = s1;
                            errs[m * EST + n0] = e0; errs[m * EST + n0 + 1] = e1;
                        }
                    }
                }
            }
        }
        __syncthreads();
    }
}

extern "C" void kernel_launch(void* const* d_in, const int* in_sizes, int n_in,
                              void* d_out, int out_size) {
    const float* S0   = (const float*)d_in[0];
    const float* tg   = (const float*)d_in[1];
    const float* dW   = (const float*)d_in[2];
    const float* W0   = (const float*)d_in[3];
    const float* b0   = (const float*)d_in[4];
    const float* W1   = (const float*)d_in[5];
    const float* b1   = (const float*)d_in[6];
    const float* W2   = (const float*)d_in[7];
    const float* b2   = (const float*)d_in[8];
    const float* W3   = (const float*)d_in[9];
    const float* b3   = (const float*)d_in[10];
    const float* Wout = (const float*)d_in[11];
    const float* bout = (const float*)d_in[12];
    float* out = (float*)d_out;

    pack_all<<<(84416 + 255) / 256, 256>>>(W0, W1, W2, W3, Wout);

    cudaFuncSetAttribute(control_solver_hmma,
                         cudaFuncAttributeMaxDynamicSharedMemorySize, SMEM_BYTES);
    control_solver_hmma<<<4096 / MT, NT, SMEM_BYTES>>>(
        S0, tg, dW, b0, b1, b2, b3, bout, out);
}